// round 16
// baseline (speedup 1.0000x reference)
#include <cuda_runtime.h>
#include <cuda_bf16.h>
#include <cstddef>
#include <cstdint>

#define HID 128
#define NS  20000
#define NM  100000
#define NSP 20096
#define NMP 100096
#define ES2M 1000000
#define EM2M 2000000
#define NLAYERS 2

#define DUAL_SMEM (4 * 128 * 68 * 4)   // 4 B-tiles as u32 [128][68]
#define QUAD_SMEM (8 * 128 * 34 * 4)   // 8 half-K B-tiles as u32 [128][34]

// ---------------- scratch (static __device__, no allocation) ----------------
__device__ __align__(16) float g_xs0[NS * HID];
__device__ __align__(16) float g_xs1[NS * HID];
__device__ __align__(16) float g_xm0[NM * HID];
__device__ __align__(16) float g_xm1[NM * HID];
__device__ float g_dF [NM];
__device__ float g_dR [NM];

// split-bf16 operand buffers (padded rows stay zero from BSS)
__device__ __align__(16) __nv_bfloat16 g_Xmh[NMP * HID];
__device__ __align__(16) __nv_bfloat16 g_Xml[NMP * HID];
__device__ __align__(16) __nv_bfloat16 g_Magh[NMP * HID];
__device__ __align__(16) __nv_bfloat16 g_Magl[NMP * HID];
__device__ __align__(16) __nv_bfloat16 g_GFh[NMP * HID];
__device__ __align__(16) __nv_bfloat16 g_GFl[NMP * HID];
__device__ __align__(16) __nv_bfloat16 g_GRh[NMP * HID];
__device__ __align__(16) __nv_bfloat16 g_GRl[NMP * HID];
__device__ __align__(16) __nv_bfloat16 g_Xsh[NSP * HID];
__device__ __align__(16) __nv_bfloat16 g_Xsl[NSP * HID];
__device__ __align__(16) __nv_bfloat16 g_Sagh[NSP * HID];
__device__ __align__(16) __nv_bfloat16 g_Sagl[NSP * HID];
__device__ __align__(16) __nv_bfloat16 g_Wth[12 * HID * HID];
__device__ __align__(16) __nv_bfloat16 g_Wtl[12 * HID * HID];

// CSR scratch
__device__ int g_cntMd[NM];
__device__ int g_cntSs[NS];
__device__ int g_cntF [NM];
__device__ int g_cntR [NM];
__device__ int g_offMd[NM + 1];
__device__ int g_offSs[NS + 1];
__device__ int g_offF [NM + 1];
__device__ int g_offR [NM + 1];
__device__ int g_curMd[NM];
__device__ int g_curSs[NS];
__device__ int g_curF [NM];
__device__ int g_curR [NM];
__device__ int g_lstMd[ES2M];
__device__ int g_lstSs[ES2M];
__device__ int g_lstF [EM2M];
__device__ int g_lstR [EM2M];
__device__ int g_bsum[4][128];

struct WPtrs { const float* p[12]; };

// ---------------- helpers ----------------
__device__ __forceinline__ void split2(float a, float b, uint32_t& h, uint32_t& l) {
    __nv_bfloat16 ha = __float2bfloat16(a), hb = __float2bfloat16(b);
    __nv_bfloat162 th(ha, hb);
    __nv_bfloat162 tl(__float2bfloat16(a - __bfloat162float(ha)),
                      __float2bfloat16(b - __bfloat162float(hb)));
    h = *reinterpret_cast<uint32_t*>(&th);
    l = *reinterpret_cast<uint32_t*>(&tl);
}

// ---------------- CSR build ----------------
__global__ void zero_counts_kernel() {
    int i = blockIdx.x * blockDim.x + threadIdx.x;
    if (i < NM) { g_cntMd[i] = 0; g_cntF[i] = 0; g_cntR[i] = 0; }
    if (i < NS) { g_cntSs[i] = 0; }
}

__global__ void hist_s2m_kernel(const int* __restrict__ src, const int* __restrict__ dst, int E) {
    int e = blockIdx.x * blockDim.x + threadIdx.x;
    if (e >= E) return;
    atomicAdd(&g_cntMd[dst[e]], 1);
    atomicAdd(&g_cntSs[src[e]], 1);
}

__global__ void hist_m2m_kernel(const int* __restrict__ src, const int* __restrict__ dst, int E) {
    int e = blockIdx.x * blockDim.x + threadIdx.x;
    if (e >= E) return;
    atomicAdd(&g_cntF[dst[e]], 1);
    atomicAdd(&g_cntR[src[e]], 1);
}

__device__ __forceinline__ void sel_arrays(int arr, const int*& cnt, int*& off, int*& cur, int& n) {
    switch (arr) {
        case 0: cnt = g_cntMd; off = g_offMd; cur = g_curMd; n = NM; break;
        case 1: cnt = g_cntSs; off = g_offSs; cur = g_curSs; n = NS; break;
        case 2: cnt = g_cntF;  off = g_offF;  cur = g_curF;  n = NM; break;
        default: cnt = g_cntR; off = g_offR;  cur = g_curR;  n = NM; break;
    }
}

__global__ void __launch_bounds__(1024) scan_partial_kernel() {
    const int* cnt; int* off; int* cur; int n;
    sel_arrays(blockIdx.y, cnt, off, cur, n);
    __shared__ int warpsums[32];
    int tid = threadIdx.x, lane = tid & 31, wid = tid >> 5;
    int i = blockIdx.x * 1024 + tid;
    int v = (i < n) ? cnt[i] : 0;
    int x = v;
#pragma unroll
    for (int o = 1; o < 32; o <<= 1) {
        int t = __shfl_up_sync(0xffffffffu, x, o);
        if (lane >= o) x += t;
    }
    if (lane == 31) warpsums[wid] = x;
    __syncthreads();
    if (wid == 0) {
        int w = warpsums[lane];
#pragma unroll
        for (int o = 1; o < 32; o <<= 1) {
            int t = __shfl_up_sync(0xffffffffu, w, o);
            if (lane >= o) w += t;
        }
        warpsums[lane] = w;
    }
    __syncthreads();
    int excl = x - v + (wid ? warpsums[wid - 1] : 0);
    if (i < n) { off[i] = excl; cur[i] = excl; }
    if (tid == 1023) g_bsum[blockIdx.y][blockIdx.x] = excl + v;
}

__global__ void __launch_bounds__(1024) scan_fix_kernel() {
    const int* cnt; int* off; int* cur; int n;
    sel_arrays(blockIdx.y, cnt, off, cur, n);
    __shared__ int sbase;
    int tid = threadIdx.x;
    if (tid < 32) {
        int s = 0;
        for (int j = tid; j < (int)blockIdx.x; j += 32) s += g_bsum[blockIdx.y][j];
#pragma unroll
        for (int o = 16; o > 0; o >>= 1) s += __shfl_xor_sync(0xffffffffu, s, o);
        if (tid == 0) sbase = s;
    }
    __syncthreads();
    int b = sbase;
    int i = blockIdx.x * 1024 + tid;
    if (i < n) { off[i] += b; cur[i] += b; }
    if (blockIdx.x == gridDim.x - 1 && tid == 0)
        off[n] = b + g_bsum[blockIdx.y][blockIdx.x];
}

__global__ void fill_s2m_kernel(const int* __restrict__ src, const int* __restrict__ dst, int E) {
    int e = blockIdx.x * blockDim.x + threadIdx.x;
    if (e >= E) return;
    int s = src[e], d = dst[e];
    g_lstMd[atomicAdd(&g_curMd[d], 1)] = s;
    g_lstSs[atomicAdd(&g_curSs[s], 1)] = d;
}

__global__ void fill_m2m_kernel(const int* __restrict__ src, const int* __restrict__ dst, int E) {
    int e = blockIdx.x * blockDim.x + threadIdx.x;
    if (e >= E) return;
    int s = src[e], d = dst[e];
    g_lstF[atomicAdd(&g_curF[d], 1)] = s;
    g_lstR[atomicAdd(&g_curR[s], 1)] = d;
}

__global__ void deg_kernel() {
    int i = blockIdx.x * blockDim.x + threadIdx.x;
    if (i < NM) {
        g_dF[i] = rsqrtf((float)g_cntF[i] + 1.0f);
        g_dR[i] = rsqrtf((float)g_cntR[i] + 1.0f);
    }
}

// ---------------- initial split conversion ----------------
__global__ void __launch_bounds__(256) split_kernel(
    const float* __restrict__ X,
    __nv_bfloat16* __restrict__ hi, __nv_bfloat16* __restrict__ lo, int n4)
{
    int i = blockIdx.x * blockDim.x + threadIdx.x;
    if (i >= n4) return;
    float4 v = reinterpret_cast<const float4*>(X)[i];
    uint2 uh, ul;
    split2(v.x, v.y, uh.x, ul.x);
    split2(v.z, v.w, uh.y, ul.y);
    reinterpret_cast<uint2*>(hi)[i] = uh;
    reinterpret_cast<uint2*>(lo)[i] = ul;
}

// all 12 weights split+transpose in one launch; grid (64, 12)
__global__ void wsplit_all_kernel(WPtrs wp) {
    int slot = blockIdx.y;
    const float* W = wp.p[slot];
    __nv_bfloat16* oh = g_Wth + (size_t)slot * HID * HID;
    __nv_bfloat16* ol = g_Wtl + (size_t)slot * HID * HID;
    int i = blockIdx.x * blockDim.x + threadIdx.x;
    if (i >= HID * HID) return;
    int k = i >> 7, n = i & 127;
    float x = W[i];
    __nv_bfloat16 h = __float2bfloat16(x);
    oh[n * 128 + k] = h;
    ol[n * 128 + k] = __float2bfloat16(x - __bfloat162float(h));
}

// ---------------- tensor-core GEMMs ----------------
__device__ __forceinline__ void mma16816(float* c,
    uint32_t a0, uint32_t a1, uint32_t a2, uint32_t a3,
    uint32_t b0, uint32_t b1)
{
    asm volatile("mma.sync.aligned.m16n8k16.row.col.f32.bf16.bf16.f32 "
        "{%0,%1,%2,%3}, {%4,%5,%6,%7}, {%8,%9}, {%0,%1,%2,%3};"
        : "+f"(c[0]), "+f"(c[1]), "+f"(c[2]), "+f"(c[3])
        : "r"(a0), "r"(a1), "r"(a2), "r"(a3), "r"(b0), "r"(b1));
}

// Dout = A1@W1 + A2@W2 (+bias1)(+relu), optional split copy (s-side)
__global__ void __launch_bounds__(256) gemm_dual(
    const __nv_bfloat16* __restrict__ A1h, const __nv_bfloat16* __restrict__ A1l,
    const __nv_bfloat16* __restrict__ B1h, const __nv_bfloat16* __restrict__ B1l,
    const __nv_bfloat16* __restrict__ A2h, const __nv_bfloat16* __restrict__ A2l,
    const __nv_bfloat16* __restrict__ B2h, const __nv_bfloat16* __restrict__ B2l,
    float* __restrict__ Dout, int M,
    const float* __restrict__ bias1, int relu,
    __nv_bfloat16* __restrict__ Oh, __nv_bfloat16* __restrict__ Ol)
{
    extern __shared__ uint32_t sb[];
    uint32_t* s1h = sb;                  // [128][68]
    uint32_t* s1l = sb + 128 * 68;
    uint32_t* s2h = sb + 2 * 128 * 68;
    uint32_t* s2l = sb + 3 * 128 * 68;
    int tid = threadIdx.x;
    for (int i = tid; i < 128 * 64; i += 256) {
        int r = i >> 6, c = i & 63;
        s1h[r * 68 + c] = reinterpret_cast<const uint32_t*>(B1h)[i];
        s1l[r * 68 + c] = reinterpret_cast<const uint32_t*>(B1l)[i];
        s2h[r * 68 + c] = reinterpret_cast<const uint32_t*>(B2h)[i];
        s2l[r * 68 + c] = reinterpret_cast<const uint32_t*>(B2l)[i];
    }
    __syncthreads();

    int warp = tid >> 5, lane = tid & 31;
    int g = lane >> 2, t4 = lane & 3;
    int m0 = blockIdx.x * 128 + warp * 16;
    const uint32_t* a1hp = reinterpret_cast<const uint32_t*>(A1h) + (size_t)m0 * 64;
    const uint32_t* a1lp = reinterpret_cast<const uint32_t*>(A1l) + (size_t)m0 * 64;
    const uint32_t* a2hp = reinterpret_cast<const uint32_t*>(A2h) + (size_t)m0 * 64;
    const uint32_t* a2lp = reinterpret_cast<const uint32_t*>(A2l) + (size_t)m0 * 64;

    float acc[16][4];
#pragma unroll
    for (int nf = 0; nf < 16; nf++)
#pragma unroll
        for (int j = 0; j < 4; j++) acc[nf][j] = 0.f;

#pragma unroll 1
    for (int k0 = 0; k0 < 8; k0++) {
        int kb = k0 * 8;
        int o0 = g * 64 + kb + t4, o1 = (g + 8) * 64 + kb + t4;
        uint32_t p0h = a1hp[o0], p1h = a1hp[o1], p2h = a1hp[o0 + 4], p3h = a1hp[o1 + 4];
        uint32_t p0l = a1lp[o0], p1l = a1lp[o1], p2l = a1lp[o0 + 4], p3l = a1lp[o1 + 4];
        uint32_t q0h = a2hp[o0], q1h = a2hp[o1], q2h = a2hp[o0 + 4], q3h = a2hp[o1 + 4];
        uint32_t q0l = a2lp[o0], q1l = a2lp[o1], q2l = a2lp[o0 + 4], q3l = a2lp[o1 + 4];
#pragma unroll
        for (int nf = 0; nf < 16; nf++) {
            int n = nf * 8 + g;
            const uint32_t* b1h = s1h + n * 68;
            const uint32_t* b1l = s1l + n * 68;
            const uint32_t* b2h = s2h + n * 68;
            const uint32_t* b2l = s2l + n * 68;
            uint32_t x0h = b1h[kb + t4], x1h = b1h[kb + t4 + 4];
            uint32_t x0l = b1l[kb + t4], x1l = b1l[kb + t4 + 4];
            uint32_t y0h = b2h[kb + t4], y1h = b2h[kb + t4 + 4];
            uint32_t y0l = b2l[kb + t4], y1l = b2l[kb + t4 + 4];
            mma16816(acc[nf], p0h, p1h, p2h, p3h, x0h, x1h);
            mma16816(acc[nf], p0h, p1h, p2h, p3h, x0l, x1l);
            mma16816(acc[nf], p0l, p1l, p2l, p3l, x0h, x1h);
            mma16816(acc[nf], q0h, q1h, q2h, q3h, y0h, y1h);
            mma16816(acc[nf], q0h, q1h, q2h, q3h, y0l, y1l);
            mma16816(acc[nf], q0l, q1l, q2l, q3l, y0h, y1h);
        }
    }

    int r0 = m0 + g, r1 = m0 + g + 8;
#pragma unroll
    for (int nf = 0; nf < 16; nf++) {
        int c = nf * 8 + t4 * 2;
        float bx = 0.f, by = 0.f;
        if (bias1) { float2 b = *reinterpret_cast<const float2*>(&bias1[c]); bx += b.x; by += b.y; }
#pragma unroll
        for (int hh = 0; hh < 2; hh++) {
            int r = hh ? r1 : r0;
            if (r >= M) continue;
            float2 o = hh ? make_float2(acc[nf][2] + bx, acc[nf][3] + by)
                          : make_float2(acc[nf][0] + bx, acc[nf][1] + by);
            if (relu) { o.x = fmaxf(o.x, 0.f); o.y = fmaxf(o.y, 0.f); }
            if (Dout) *reinterpret_cast<float2*>(&Dout[(size_t)r * 128 + c]) = o;
            if (Oh) {
                uint32_t h, l;
                split2(o.x, o.y, h, l);
                *reinterpret_cast<uint32_t*>(&Oh[(size_t)r * 128 + c]) = h;
                *reinterpret_cast<uint32_t*>(&Ol[(size_t)r * 128 + c]) = l;
            }
        }
    }
}

// Quad: xmo = relu(Xm@W1 + Mag@W2 + GF@W3 + GR@W4 + b1+b2+b3) + split copy.
// B tiles streamed in 2 K-halves through smem ([128][34] u32 per matrix-half).
__global__ void __launch_bounds__(256) gemm_quad(
    const __nv_bfloat16* __restrict__ A1h, const __nv_bfloat16* __restrict__ A1l,
    const __nv_bfloat16* __restrict__ B1h, const __nv_bfloat16* __restrict__ B1l,
    const __nv_bfloat16* __restrict__ A2h, const __nv_bfloat16* __restrict__ A2l,
    const __nv_bfloat16* __restrict__ B2h, const __nv_bfloat16* __restrict__ B2l,
    const __nv_bfloat16* __restrict__ A3h, const __nv_bfloat16* __restrict__ A3l,
    const __nv_bfloat16* __restrict__ B3h, const __nv_bfloat16* __restrict__ B3l,
    const __nv_bfloat16* __restrict__ A4h, const __nv_bfloat16* __restrict__ A4l,
    const __nv_bfloat16* __restrict__ B4h, const __nv_bfloat16* __restrict__ B4l,
    float* __restrict__ Dout, int M,
    const float* __restrict__ bias1, const float* __restrict__ bias2,
    const float* __restrict__ bias3,
    __nv_bfloat16* __restrict__ Oh, __nv_bfloat16* __restrict__ Ol)
{
    extern __shared__ uint32_t sb[];
    const uint32_t* Bsrc[8] = {
        reinterpret_cast<const uint32_t*>(B1h), reinterpret_cast<const uint32_t*>(B1l),
        reinterpret_cast<const uint32_t*>(B2h), reinterpret_cast<const uint32_t*>(B2l),
        reinterpret_cast<const uint32_t*>(B3h), reinterpret_cast<const uint32_t*>(B3l),
        reinterpret_cast<const uint32_t*>(B4h), reinterpret_cast<const uint32_t*>(B4l) };

    int tid = threadIdx.x;
    int warp = tid >> 5, lane = tid & 31;
    int g = lane >> 2, t4 = lane & 3;
    int m0 = blockIdx.x * 128 + warp * 16;

    const uint32_t* ah[4] = {
        reinterpret_cast<const uint32_t*>(A1h) + (size_t)m0 * 64,
        reinterpret_cast<const uint32_t*>(A2h) + (size_t)m0 * 64,
        reinterpret_cast<const uint32_t*>(A3h) + (size_t)m0 * 64,
        reinterpret_cast<const uint32_t*>(A4h) + (size_t)m0 * 64 };
    const uint32_t* al[4] = {
        reinterpret_cast<const uint32_t*>(A1l) + (size_t)m0 * 64,
        reinterpret_cast<const uint32_t*>(A2l) + (size_t)m0 * 64,
        reinterpret_cast<const uint32_t*>(A3l) + (size_t)m0 * 64,
        reinterpret_cast<const uint32_t*>(A4l) + (size_t)m0 * 64 };

    float acc[16][4];
#pragma unroll
    for (int nf = 0; nf < 16; nf++)
#pragma unroll
        for (int j = 0; j < 4; j++) acc[nf][j] = 0.f;

#pragma unroll 1
    for (int hh2 = 0; hh2 < 2; hh2++) {
        __syncthreads();   // protect prior half's smem reads before overwrite
#pragma unroll 1
        for (int t = 0; t < 8; t++) {
            const uint32_t* src = Bsrc[t];
            uint32_t* dstT = sb + t * (128 * 34);
            for (int i = tid; i < 128 * 32; i += 256) {
                int r = i >> 5, c = i & 31;
                dstT[r * 34 + c] = src[r * 64 + hh2 * 32 + c];
            }
        }
        __syncthreads();
#pragma unroll 1
        for (int k0 = 0; k0 < 4; k0++) {
            int kb = k0 * 8;
            int co = hh2 * 32 + kb + t4;
            int o0 = g * 64 + co, o1 = (g + 8) * 64 + co;
            uint32_t aH[4][4], aL[4][4];
#pragma unroll
            for (int op = 0; op < 4; op++) {
                aH[op][0] = ah[op][o0]; aH[op][1] = ah[op][o1];
                aH[op][2] = ah[op][o0 + 4]; aH[op][3] = ah[op][o1 + 4];
                aL[op][0] = al[op][o0]; aL[op][1] = al[op][o1];
                aL[op][2] = al[op][o0 + 4]; aL[op][3] = al[op][o1 + 4];
            }
#pragma unroll
            for (int nf = 0; nf < 16; nf++) {
                int n = nf * 8 + g;
#pragma unroll
                for (int op = 0; op < 4; op++) {
                    const uint32_t* bh = sb + (op * 2) * (128 * 34) + n * 34;
                    const uint32_t* bl = sb + (op * 2 + 1) * (128 * 34) + n * 34;
                    uint32_t x0h = bh[kb + t4], x1h = bh[kb + t4 + 4];
                    uint32_t x0l = bl[kb + t4], x1l = bl[kb + t4 + 4];
                    mma16816(acc[nf], aH[op][0], aH[op][1], aH[op][2], aH[op][3], x0h, x1h);
                    mma16816(acc[nf], aH[op][0], aH[op][1], aH[op][2], aH[op][3], x0l, x1l);
                    mma16816(acc[nf], aL[op][0], aL[op][1], aL[op][2], aL[op][3], x0h, x1h);
                }
            }
        }
    }

    int r0 = m0 + g, r1 = m0 + g + 8;
#pragma unroll
    for (int nf = 0; nf < 16; nf++) {
        int c = nf * 8 + t4 * 2;
        float2 b1 = *reinterpret_cast<const float2*>(&bias1[c]);
        float2 b2 = *reinterpret_cast<const float2*>(&bias2[c]);
        float2 b3 = *reinterpret_cast<const float2*>(&bias3[c]);
        float bx = b1.x + b2.x + b3.x, by = b1.y + b2.y + b3.y;
#pragma unroll
        for (int hh = 0; hh < 2; hh++) {
            int r = hh ? r1 : r0;
            if (r >= M) continue;
            float2 o = hh ? make_float2(acc[nf][2] + bx, acc[nf][3] + by)
                          : make_float2(acc[nf][0] + bx, acc[nf][1] + by);
            o.x = fmaxf(o.x, 0.f); o.y = fmaxf(o.y, 0.f);
            *reinterpret_cast<float2*>(&Dout[(size_t)r * 128 + c]) = o;
            uint32_t h, l;
            split2(o.x, o.y, h, l);
            *reinterpret_cast<uint32_t*>(&Oh[(size_t)r * 128 + c]) = h;
            *reinterpret_cast<uint32_t*>(&Ol[(size_t)r * 128 + c]) = l;
        }
    }
}

// ---------------- gathers (warp per dst row, 2-way unroll — proven) ----------------
__global__ void __launch_bounds__(256) gather_mean_split_kernel(
    const int* __restrict__ off, const int* __restrict__ lst,
    const float* __restrict__ X,
    __nv_bfloat16* __restrict__ Oh, __nv_bfloat16* __restrict__ Ol, int n)
{
    int w = (blockIdx.x * blockDim.x + threadIdx.x) >> 5;
    if (w >= n) return;
    int lane = threadIdx.x & 31;
    int s = off[w], e = off[w + 1];
    float4 a0 = make_float4(0.f, 0.f, 0.f, 0.f);
    float4 a1 = make_float4(0.f, 0.f, 0.f, 0.f);
    int i = s;
    for (; i + 1 < e; i += 2) {
        int p0 = lst[i], p1 = lst[i + 1];
        float4 v0 = *reinterpret_cast<const float4*>(&X[(size_t)p0 * HID + lane * 4]);
        float4 v1 = *reinterpret_cast<const float4*>(&X[(size_t)p1 * HID + lane * 4]);
        a0.x += v0.x; a0.y += v0.y; a0.z += v0.z; a0.w += v0.w;
        a1.x += v1.x; a1.y += v1.y; a1.z += v1.z; a1.w += v1.w;
    }
    if (i < e) {
        int p0 = lst[i];
        float4 v0 = *reinterpret_cast<const float4*>(&X[(size_t)p0 * HID + lane * 4]);
        a0.x += v0.x; a0.y += v0.y; a0.z += v0.z; a0.w += v0.w;
    }
    float inv = 1.0f / fmaxf((float)(e - s), 1.0f);
    float ox = (a0.x + a1.x) * inv, oy = (a0.y + a1.y) * inv;
    float oz = (a0.z + a1.z) * inv, ow = (a0.w + a1.w) * inv;
    uint2 uh, ul;
    split2(ox, oy, uh.x, ul.x);
    split2(oz, ow, uh.y, ul.y);
    reinterpret_cast<uint2*>(&Oh[(size_t)w * HID])[lane] = uh;
    reinterpret_cast<uint2*>(&Ol[(size_t)w * HID])[lane] = ul;
}

// GCN pre-aggregation over x_m (both directions), outputs split GF/GR
__global__ void __launch_bounds__(256) gcn_pre_kernel(const float* __restrict__ X)
{
    int w = (blockIdx.x * blockDim.x + threadIdx.x) >> 5;
    if (w >= NM) return;
    int lane = threadIdx.x & 31;
    size_t ro = (size_t)w * HID + lane * 4;

    float4 aF = make_float4(0.f, 0.f, 0.f, 0.f);
    {
        int s = g_offF[w], e = g_offF[w + 1];
        float4 t1 = make_float4(0.f, 0.f, 0.f, 0.f);
        int i = s;
        for (; i + 1 < e; i += 2) {
            int p0 = g_lstF[i], p1 = g_lstF[i + 1];
            float w0 = g_dF[p0], w1 = g_dF[p1];
            float4 v0 = *reinterpret_cast<const float4*>(&X[(size_t)p0 * HID + lane * 4]);
            float4 v1 = *reinterpret_cast<const float4*>(&X[(size_t)p1 * HID + lane * 4]);
            aF.x += w0 * v0.x; aF.y += w0 * v0.y; aF.z += w0 * v0.z; aF.w += w0 * v0.w;
            t1.x += w1 * v1.x; t1.y += w1 * v1.y; t1.z += w1 * v1.z; t1.w += w1 * v1.w;
        }
        if (i < e) {
            int p0 = g_lstF[i];
            float w0 = g_dF[p0];
            float4 v0 = *reinterpret_cast<const float4*>(&X[(size_t)p0 * HID + lane * 4]);
            aF.x += w0 * v0.x; aF.y += w0 * v0.y; aF.z += w0 * v0.z; aF.w += w0 * v0.w;
        }
        aF.x += t1.x; aF.y += t1.y; aF.z += t1.z; aF.w += t1.w;
    }
    float4 aR = make_float4(0.f, 0.f, 0.f, 0.f);
    {
        int s = g_offR[w], e = g_offR[w + 1];
        float4 t1 = make_float4(0.f, 0.f, 0.f, 0.f);
        int i = s;
        for (; i + 1 < e; i += 2) {
            int p0 = g_lstR[i], p1 = g_lstR[i + 1];
            float w0 = g_dR[p0], w1 = g_dR[p1];
            float4 v0 = *reinterpret_cast<const float4*>(&X[(size_t)p0 * HID + lane * 4]);
            float4 v1 = *reinterpret_cast<const float4*>(&X[(size_t)p1 * HID + lane * 4]);
            aR.x += w0 * v0.x; aR.y += w0 * v0.y; aR.z += w0 * v0.z; aR.w += w0 * v0.w;
            t1.x += w1 * v1.x; t1.y += w1 * v1.y; t1.z += w1 * v1.z; t1.w += w1 * v1.w;
        }
        if (i < e) {
            int p0 = g_lstR[i];
            float w0 = g_dR[p0];
            float4 v0 = *reinterpret_cast<const float4*>(&X[(size_t)p0 * HID + lane * 4]);
            aR.x += w0 * v0.x; aR.y += w0 * v0.y; aR.z += w0 * v0.z; aR.w += w0 * v0.w;
        }
        aR.x += t1.x; aR.y += t1.y; aR.z += t1.z; aR.w += t1.w;
    }

    float f = g_dF[w], r = g_dR[w];
    float f2 = f * f, r2 = r * r;
    float4 xv = *reinterpret_cast<const float4*>(&X[ro]);
    float fx = f * aF.x + f2 * xv.x, fy = f * aF.y + f2 * xv.y;
    float fz = f * aF.z + f2 * xv.z, fw = f * aF.w + f2 * xv.w;
    float rx = r * aR.x + r2 * xv.x, ry = r * aR.y + r2 * xv.y;
    float rz = r * aR.z + r2 * xv.z, rw = r * aR.w + r2 * xv.w;
    uint2 uh, ul;
    split2(fx, fy, uh.x, ul.x);
    split2(fz, fw, uh.y, ul.y);
    reinterpret_cast<uint2*>(&g_GFh[(size_t)w * HID])[lane] = uh;
    reinterpret_cast<uint2*>(&g_GFl[(size_t)w * HID])[lane] = ul;
    split2(rx, ry, uh.x, ul.x);
    split2(rz, rw, uh.y, ul.y);
    reinterpret_cast<uint2*>(&g_GRh[(size_t)w * HID])[lane] = uh;
    reinterpret_cast<uint2*>(&g_GRl[(size_t)w * HID])[lane] = ul;
}

// ---------------- classifier ----------------
__global__ void __launch_bounds__(256) classify_kernel(
    const int* __restrict__ ls, const int* __restrict__ ld,
    const float* __restrict__ XS, const float* __restrict__ XM,
    float* __restrict__ out, int E)
{
    long long t = (long long)blockIdx.x * blockDim.x + threadIdx.x;
    int e = (int)(t >> 5);
    if (e >= E) return;
    int lane = (int)(t & 31);
    int s = ls[e], d = ld[e];
    float4 a = *reinterpret_cast<const float4*>(&XS[(size_t)s * HID + lane * 4]);
    float4 b = *reinterpret_cast<const float4*>(&XM[(size_t)d * HID + lane * 4]);
    float p = a.x * b.x + a.y * b.y + a.z * b.z + a.w * b.w;
#pragma unroll
    for (int o = 16; o > 0; o >>= 1) p += __shfl_xor_sync(0xffffffffu, p, o);
    if (lane == 0) out[e] = p;
}

// ---------------- host ----------------
extern "C" void kernel_launch(void* const* d_in, const int* in_sizes, int n_in,
                              void* d_out, int out_size)
{
    const int*   s2m_src = (const int*)d_in[0];
    const int*   s2m_dst = (const int*)d_in[1];
    const int*   m2m_src = (const int*)d_in[2];
    const int*   m2m_dst = (const int*)d_in[3];
    const int*   lbl_src = (const int*)d_in[4];
    const int*   lbl_dst = (const int*)d_in[5];
    const float* srna    = (const float*)d_in[6];
    const float* mrna    = (const float*)d_in[7];
    const float* sWl     = (const float*)d_in[8];
    const float* sbl     = (const float*)d_in[9];
    const float* sWr     = (const float*)d_in[10];
    const float* rWl     = (const float*)d_in[11];
    const float* rbl     = (const float*)d_in[12];
    const float* rWr     = (const float*)d_in[13];
    const float* gFW     = (const float*)d_in[14];
    const float* gFb     = (const float*)d_in[15];
    const float* gRW     = (const float*)d_in[16];
    const float* gRb     = (const float*)d_in[17];

    const int Es2m = in_sizes[0];
    const int Em2m = in_sizes[2];
    const int Elbl = in_sizes[4];

    float *xs0, *xs1, *xm0, *xm1;
    int *offMd, *offSs, *lstMd, *lstSs;
    __nv_bfloat16 *Xmh, *Xml, *Magh, *Magl, *GFh, *GFl, *GRh, *GRl;
    __nv_bfloat16 *Xsh, *Xsl, *Sagh, *Sagl, *Wth, *Wtl;
    cudaGetSymbolAddress((void**)&xs0, g_xs0);
    cudaGetSymbolAddress((void**)&xs1, g_xs1);
    cudaGetSymbolAddress((void**)&xm0, g_xm0);
    cudaGetSymbolAddress((void**)&xm1, g_xm1);
    cudaGetSymbolAddress((void**)&offMd, g_offMd);
    cudaGetSymbolAddress((void**)&offSs, g_offSs);
    cudaGetSymbolAddress((void**)&lstMd, g_lstMd);
    cudaGetSymbolAddress((void**)&lstSs, g_lstSs);
    cudaGetSymbolAddress((void**)&Xmh, g_Xmh);
    cudaGetSymbolAddress((void**)&Xml, g_Xml);
    cudaGetSymbolAddress((void**)&Magh, g_Magh);
    cudaGetSymbolAddress((void**)&Magl, g_Magl);
    cudaGetSymbolAddress((void**)&GFh, g_GFh);
    cudaGetSymbolAddress((void**)&GFl, g_GFl);
    cudaGetSymbolAddress((void**)&GRh, g_GRh);
    cudaGetSymbolAddress((void**)&GRl, g_GRl);
    cudaGetSymbolAddress((void**)&Xsh, g_Xsh);
    cudaGetSymbolAddress((void**)&Xsl, g_Xsl);
    cudaGetSymbolAddress((void**)&Sagh, g_Sagh);
    cudaGetSymbolAddress((void**)&Sagl, g_Sagl);
    cudaGetSymbolAddress((void**)&Wth, g_Wth);
    cudaGetSymbolAddress((void**)&Wtl, g_Wtl);

    cudaFuncSetAttribute(gemm_dual,
                         cudaFuncAttributeMaxDynamicSharedMemorySize, DUAL_SMEM);
    cudaFuncSetAttribute(gemm_quad,
                         cudaFuncAttributeMaxDynamicSharedMemorySize, QUAD_SMEM);

    static cudaStream_t s2 = nullptr;
    static cudaEvent_t ev0, evSplit, evCsr, evS;
    static cudaEvent_t evMag[NLAYERS], evM[NLAYERS];
    if (!s2) {
        cudaStreamCreateWithFlags(&s2, cudaStreamNonBlocking);
        cudaEventCreateWithFlags(&ev0, cudaEventDisableTiming);
        cudaEventCreateWithFlags(&evSplit, cudaEventDisableTiming);
        cudaEventCreateWithFlags(&evCsr, cudaEventDisableTiming);
        cudaEventCreateWithFlags(&evS, cudaEventDisableTiming);
        for (int i = 0; i < NLAYERS; i++) {
            cudaEventCreateWithFlags(&evMag[i], cudaEventDisableTiming);
            cudaEventCreateWithFlags(&evM[i], cudaEventDisableTiming);
        }
    }

    const size_t WSZ = (size_t)HID * HID;
    const unsigned gm = NMP / 128;   // 782
    const unsigned gs = NSP / 128;   // 157

    // ---- fork: side does initial feature splits; main: batched weight split + CSR ----
    cudaEventRecord(ev0, 0);
    cudaStreamWaitEvent(s2, ev0, 0);
    split_kernel<<<(NM * 32 + 255) / 256, 256, 0, s2>>>(mrna, Xmh, Xml, NM * 32);
    split_kernel<<<(NS * 32 + 255) / 256, 256, 0, s2>>>(srna, Xsh, Xsl, NS * 32);
    cudaEventRecord(evSplit, s2);

    {
        WPtrs wp;
        for (int l = 0; l < NLAYERS; l++) {
            wp.p[l * 6 + 0] = sWl + l * WSZ;
            wp.p[l * 6 + 1] = sWr + l * WSZ;
            wp.p[l * 6 + 2] = rWl + l * WSZ;
            wp.p[l * 6 + 3] = rWr + l * WSZ;
            wp.p[l * 6 + 4] = gFW + l * WSZ;
            wp.p[l * 6 + 5] = gRW + l * WSZ;
        }
        dim3 g(64, 12);
        wsplit_all_kernel<<<g, 256>>>(wp);
    }
    zero_counts_kernel<<<(NM + 255) / 256, 256>>>();
    hist_s2m_kernel<<<(Es2m + 255) / 256, 256>>>(s2m_src, s2m_dst, Es2m);
    hist_m2m_kernel<<<(Em2m + 255) / 256, 256>>>(m2m_src, m2m_dst, Em2m);
    {
        dim3 g((NM + 1023) / 1024, 4);
        scan_partial_kernel<<<g, 1024>>>();
        scan_fix_kernel<<<g, 1024>>>();
    }
    fill_s2m_kernel<<<(Es2m + 255) / 256, 256>>>(s2m_src, s2m_dst, Es2m);
    fill_m2m_kernel<<<(Em2m + 255) / 256, 256>>>(m2m_src, m2m_dst, Em2m);
    deg_kernel<<<(NM + 255) / 256, 256>>>();
    cudaEventRecord(evCsr, 0);
    cudaStreamWaitEvent(s2, evCsr, 0);   // side gathers need CSR
    cudaStreamWaitEvent(0, evSplit, 0);  // main quad reads Xm split

    const float* xsi = srna;
    const float* xmi = mrna;

    for (int l = 0; l < NLAYERS; l++) {
        float* xso = (l == 0) ? xs0 : xs1;
        float* xmo = (l == 0) ? xm0 : xm1;
        int s6 = l * 6;

        // side must not overwrite Mag while prev quad still reads it; also Ss gather needs xmo
        if (l > 0) cudaStreamWaitEvent(s2, evM[l - 1], 0);

        // ---- side stream: Md gather -> (evMag) -> Ss gather -> s-dual ----
        gather_mean_split_kernel<<<(NM * 32 + 255) / 256, 256, 0, s2>>>(offMd, lstMd, xsi, Magh, Magl, NM);
        cudaEventRecord(evMag[l], s2);
        gather_mean_split_kernel<<<(NS * 32 + 255) / 256, 256, 0, s2>>>(offSs, lstSs, xmi, Sagh, Sagl, NS);
        gemm_dual<<<gs, 256, DUAL_SMEM, s2>>>(
            Xsh, Xsl, Wth + (s6 + 3) * WSZ, Wtl + (s6 + 3) * WSZ,     // x_s @ rWr
            Sagh, Sagl, Wth + (s6 + 2) * WSZ, Wtl + (s6 + 2) * WSZ,   // mean @ rWl
            xso, NS, rbl + l * HID, 1, Xsh, Xsl);
        if (l == NLAYERS - 1) cudaEventRecord(evS, s2);

        // ---- main stream: gcn_pre (memory) then quad (tensor) ----
        gcn_pre_kernel<<<(NM * 32 + 255) / 256, 256>>>(xmi);
        cudaStreamWaitEvent(0, evMag[l], 0);
        gemm_quad<<<gm, 256, QUAD_SMEM>>>(
            Xmh, Xml, Wth + (s6 + 1) * WSZ, Wtl + (s6 + 1) * WSZ,     // x_m @ sWr
            Magh, Magl, Wth + (s6 + 0) * WSZ, Wtl + (s6 + 0) * WSZ,   // mean @ sWl
            GFh, GFl, Wth + (s6 + 4) * WSZ, Wtl + (s6 + 4) * WSZ,     // gF_in @ gFW
            GRh, GRl, Wth + (s6 + 5) * WSZ, Wtl + (s6 + 5) * WSZ,     // gR_in @ gRW
            xmo, NM, sbl + l * HID, gFb + l * HID, gRb + l * HID, Xmh, Xml);
        cudaEventRecord(evM[l], 0);

        xsi = xso;
        xmi = xmo;
    }

    cudaStreamWaitEvent(0, evS, 0);
    {
        long long th = (long long)Elbl * 32;
        classify_kernel<<<(unsigned)((th + 255) / 256), 256>>>(lbl_src, lbl_dst, xsi, xmi, (float*)d_out, Elbl);
    }
}

// round 17
// speedup vs baseline: 1.5596x; 1.5596x over previous
#include <cuda_runtime.h>
#include <cuda_bf16.h>
#include <cstddef>
#include <cstdint>

#define HID 128
#define NS  20000
#define NM  100000
#define NSP 20224
#define NMP 100352
#define ES2M 1000000
#define EM2M 2000000
#define NLAYERS 2

#define DUAL_SMEM (4 * 128 * 68 * 4)   // 4 B-tiles as u32 [128][68]

// ---------------- scratch (static __device__, no allocation) ----------------
__device__ __align__(16) float g_xs0[NS * HID];
__device__ __align__(16) float g_xs1[NS * HID];
__device__ __align__(16) float g_xm0[NM * HID];
__device__ __align__(16) float g_xm1[NM * HID];
__device__ __align__(16) float g_macc[NM * HID];
__device__ float g_dF [NM];
__device__ float g_dR [NM];

// split-bf16 operand buffers (padded rows stay zero from BSS)
__device__ __align__(16) __nv_bfloat16 g_Xmh[NMP * HID];
__device__ __align__(16) __nv_bfloat16 g_Xml[NMP * HID];
__device__ __align__(16) __nv_bfloat16 g_Magh[NMP * HID];
__device__ __align__(16) __nv_bfloat16 g_Magl[NMP * HID];
__device__ __align__(16) __nv_bfloat16 g_GFh[NMP * HID];
__device__ __align__(16) __nv_bfloat16 g_GFl[NMP * HID];
__device__ __align__(16) __nv_bfloat16 g_GRh[NMP * HID];
__device__ __align__(16) __nv_bfloat16 g_GRl[NMP * HID];
__device__ __align__(16) __nv_bfloat16 g_Xsh[NSP * HID];
__device__ __align__(16) __nv_bfloat16 g_Xsl[NSP * HID];
__device__ __align__(16) __nv_bfloat16 g_Sagh[NSP * HID];
__device__ __align__(16) __nv_bfloat16 g_Sagl[NSP * HID];
__device__ __align__(16) __nv_bfloat16 g_Wth[12 * HID * HID];
__device__ __align__(16) __nv_bfloat16 g_Wtl[12 * HID * HID];

// CSR scratch
__device__ int g_cntMd[NM];
__device__ int g_cntSs[NS];
__device__ int g_cntF [NM];
__device__ int g_cntR [NM];
__device__ int g_offMd[NM + 1];
__device__ int g_offSs[NS + 1];
__device__ int g_offF [NM + 1];
__device__ int g_offR [NM + 1];
__device__ int g_curMd[NM];
__device__ int g_curSs[NS];
__device__ int g_curF [NM];
__device__ int g_curR [NM];
__device__ int g_lstMd[ES2M];
__device__ int g_lstSs[ES2M];
__device__ int g_lstF [EM2M];
__device__ int g_lstR [EM2M];
__device__ int g_bsum[4][128];

struct WPtrs { const float* p[12]; };

// ---------------- helpers ----------------
__device__ __forceinline__ void split2(float a, float b, uint32_t& h, uint32_t& l) {
    __nv_bfloat16 ha = __float2bfloat16(a), hb = __float2bfloat16(b);
    __nv_bfloat162 th(ha, hb);
    __nv_bfloat162 tl(__float2bfloat16(a - __bfloat162float(ha)),
                      __float2bfloat16(b - __bfloat162float(hb)));
    h = *reinterpret_cast<uint32_t*>(&th);
    l = *reinterpret_cast<uint32_t*>(&tl);
}

// ---------------- CSR build ----------------
__global__ void zero_counts_kernel() {
    int i = blockIdx.x * blockDim.x + threadIdx.x;
    if (i < NM) { g_cntMd[i] = 0; g_cntF[i] = 0; g_cntR[i] = 0; }
    if (i < NS) { g_cntSs[i] = 0; }
}

__global__ void hist_s2m_kernel(const int* __restrict__ src, const int* __restrict__ dst, int E) {
    int e = blockIdx.x * blockDim.x + threadIdx.x;
    if (e >= E) return;
    atomicAdd(&g_cntMd[dst[e]], 1);
    atomicAdd(&g_cntSs[src[e]], 1);
}

__global__ void hist_m2m_kernel(const int* __restrict__ src, const int* __restrict__ dst, int E) {
    int e = blockIdx.x * blockDim.x + threadIdx.x;
    if (e >= E) return;
    atomicAdd(&g_cntF[dst[e]], 1);
    atomicAdd(&g_cntR[src[e]], 1);
}

__device__ __forceinline__ void sel_arrays(int arr, const int*& cnt, int*& off, int*& cur, int& n) {
    switch (arr) {
        case 0: cnt = g_cntMd; off = g_offMd; cur = g_curMd; n = NM; break;
        case 1: cnt = g_cntSs; off = g_offSs; cur = g_curSs; n = NS; break;
        case 2: cnt = g_cntF;  off = g_offF;  cur = g_curF;  n = NM; break;
        default: cnt = g_cntR; off = g_offR;  cur = g_curR;  n = NM; break;
    }
}

__global__ void __launch_bounds__(1024) scan_partial_kernel() {
    const int* cnt; int* off; int* cur; int n;
    sel_arrays(blockIdx.y, cnt, off, cur, n);
    __shared__ int warpsums[32];
    int tid = threadIdx.x, lane = tid & 31, wid = tid >> 5;
    int i = blockIdx.x * 1024 + tid;
    int v = (i < n) ? cnt[i] : 0;
    int x = v;
#pragma unroll
    for (int o = 1; o < 32; o <<= 1) {
        int t = __shfl_up_sync(0xffffffffu, x, o);
        if (lane >= o) x += t;
    }
    if (lane == 31) warpsums[wid] = x;
    __syncthreads();
    if (wid == 0) {
        int w = warpsums[lane];
#pragma unroll
        for (int o = 1; o < 32; o <<= 1) {
            int t = __shfl_up_sync(0xffffffffu, w, o);
            if (lane >= o) w += t;
        }
        warpsums[lane] = w;
    }
    __syncthreads();
    int excl = x - v + (wid ? warpsums[wid - 1] : 0);
    if (i < n) { off[i] = excl; cur[i] = excl; }
    if (tid == 1023) g_bsum[blockIdx.y][blockIdx.x] = excl + v;
}

__global__ void __launch_bounds__(1024) scan_fix_kernel() {
    const int* cnt; int* off; int* cur; int n;
    sel_arrays(blockIdx.y, cnt, off, cur, n);
    __shared__ int sbase;
    int tid = threadIdx.x;
    if (tid < 32) {
        int s = 0;
        for (int j = tid; j < (int)blockIdx.x; j += 32) s += g_bsum[blockIdx.y][j];
#pragma unroll
        for (int o = 16; o > 0; o >>= 1) s += __shfl_xor_sync(0xffffffffu, s, o);
        if (tid == 0) sbase = s;
    }
    __syncthreads();
    int b = sbase;
    int i = blockIdx.x * 1024 + tid;
    if (i < n) { off[i] += b; cur[i] += b; }
    if (blockIdx.x == gridDim.x - 1 && tid == 0)
        off[n] = b + g_bsum[blockIdx.y][blockIdx.x];
}

__global__ void fill_s2m_kernel(const int* __restrict__ src, const int* __restrict__ dst, int E) {
    int e = blockIdx.x * blockDim.x + threadIdx.x;
    if (e >= E) return;
    int s = src[e], d = dst[e];
    g_lstMd[atomicAdd(&g_curMd[d], 1)] = s;
    g_lstSs[atomicAdd(&g_curSs[s], 1)] = d;
}

__global__ void fill_m2m_kernel(const int* __restrict__ src, const int* __restrict__ dst, int E) {
    int e = blockIdx.x * blockDim.x + threadIdx.x;
    if (e >= E) return;
    int s = src[e], d = dst[e];
    g_lstF[atomicAdd(&g_curF[d], 1)] = s;
    g_lstR[atomicAdd(&g_curR[s], 1)] = d;
}

__global__ void deg_kernel() {
    int i = blockIdx.x * blockDim.x + threadIdx.x;
    if (i < NM) {
        g_dF[i] = rsqrtf((float)g_cntF[i] + 1.0f);
        g_dR[i] = rsqrtf((float)g_cntR[i] + 1.0f);
    }
}

// ---------------- initial split conversion ----------------
__global__ void __launch_bounds__(256) split_kernel(
    const float* __restrict__ X,
    __nv_bfloat16* __restrict__ hi, __nv_bfloat16* __restrict__ lo, int n4)
{
    int i = blockIdx.x * blockDim.x + threadIdx.x;
    if (i >= n4) return;
    float4 v = reinterpret_cast<const float4*>(X)[i];
    uint2 uh, ul;
    split2(v.x, v.y, uh.x, ul.x);
    split2(v.z, v.w, uh.y, ul.y);
    reinterpret_cast<uint2*>(hi)[i] = uh;
    reinterpret_cast<uint2*>(lo)[i] = ul;
}

// all 12 weights split+transpose in one launch; grid (64, 12)
__global__ void wsplit_all_kernel(WPtrs wp) {
    int slot = blockIdx.y;
    const float* W = wp.p[slot];
    __nv_bfloat16* oh = g_Wth + (size_t)slot * HID * HID;
    __nv_bfloat16* ol = g_Wtl + (size_t)slot * HID * HID;
    int i = blockIdx.x * blockDim.x + threadIdx.x;
    if (i >= HID * HID) return;
    int k = i >> 7, n = i & 127;
    float x = W[i];
    __nv_bfloat16 h = __float2bfloat16(x);
    oh[n * 128 + k] = h;
    ol[n * 128 + k] = __float2bfloat16(x - __bfloat162float(h));
}

// ---------------- dual tensor-core GEMM (512 threads, M=256 tile) ----------------
__device__ __forceinline__ void mma16816(float* c,
    uint32_t a0, uint32_t a1, uint32_t a2, uint32_t a3,
    uint32_t b0, uint32_t b1)
{
    asm volatile("mma.sync.aligned.m16n8k16.row.col.f32.bf16.bf16.f32 "
        "{%0,%1,%2,%3}, {%4,%5,%6,%7}, {%8,%9}, {%0,%1,%2,%3};"
        : "+f"(c[0]), "+f"(c[1]), "+f"(c[2]), "+f"(c[3])
        : "r"(a0), "r"(a1), "r"(a2), "r"(a3), "r"(b0), "r"(b1));
}

// Dout = A1@W1 + A2@W2 (+bias1)(+bias2)(+ACCsrc)(relu), optional split copy
__global__ void __launch_bounds__(512) gemm_dual(
    const __nv_bfloat16* __restrict__ A1h, const __nv_bfloat16* __restrict__ A1l,
    const __nv_bfloat16* __restrict__ B1h, const __nv_bfloat16* __restrict__ B1l,
    const __nv_bfloat16* __restrict__ A2h, const __nv_bfloat16* __restrict__ A2l,
    const __nv_bfloat16* __restrict__ B2h, const __nv_bfloat16* __restrict__ B2l,
    const float* __restrict__ ACCsrc, float* __restrict__ Dout, int M,
    const float* __restrict__ bias1, const float* __restrict__ bias2, int relu,
    __nv_bfloat16* __restrict__ Oh, __nv_bfloat16* __restrict__ Ol)
{
    extern __shared__ uint32_t sb[];
    uint32_t* s1h = sb;                  // [128][68]
    uint32_t* s1l = sb + 128 * 68;
    uint32_t* s2h = sb + 2 * 128 * 68;
    uint32_t* s2l = sb + 3 * 128 * 68;
    int tid = threadIdx.x;
    for (int i = tid; i < 128 * 64; i += 512) {
        int r = i >> 6, c = i & 63;
        s1h[r * 68 + c] = reinterpret_cast<const uint32_t*>(B1h)[i];
        s1l[r * 68 + c] = reinterpret_cast<const uint32_t*>(B1l)[i];
        s2h[r * 68 + c] = reinterpret_cast<const uint32_t*>(B2h)[i];
        s2l[r * 68 + c] = reinterpret_cast<const uint32_t*>(B2l)[i];
    }
    __syncthreads();

    int warp = tid >> 5, lane = tid & 31;   // 16 warps
    int g = lane >> 2, t4 = lane & 3;
    int m0 = blockIdx.x * 256 + warp * 16;
    const uint32_t* a1hp = reinterpret_cast<const uint32_t*>(A1h) + (size_t)m0 * 64;
    const uint32_t* a1lp = reinterpret_cast<const uint32_t*>(A1l) + (size_t)m0 * 64;
    const uint32_t* a2hp = reinterpret_cast<const uint32_t*>(A2h) + (size_t)m0 * 64;
    const uint32_t* a2lp = reinterpret_cast<const uint32_t*>(A2l) + (size_t)m0 * 64;

    float acc[16][4];
#pragma unroll
    for (int nf = 0; nf < 16; nf++)
#pragma unroll
        for (int j = 0; j < 4; j++) acc[nf][j] = 0.f;

#pragma unroll 1
    for (int k0 = 0; k0 < 8; k0++) {
        int kb = k0 * 8;
        int o0 = g * 64 + kb + t4, o1 = (g + 8) * 64 + kb + t4;
        uint32_t p0h = a1hp[o0], p1h = a1hp[o1], p2h = a1hp[o0 + 4], p3h = a1hp[o1 + 4];
        uint32_t p0l = a1lp[o0], p1l = a1lp[o1], p2l = a1lp[o0 + 4], p3l = a1lp[o1 + 4];
        uint32_t q0h = a2hp[o0], q1h = a2hp[o1], q2h = a2hp[o0 + 4], q3h = a2hp[o1 + 4];
        uint32_t q0l = a2lp[o0], q1l = a2lp[o1], q2l = a2lp[o0 + 4], q3l = a2lp[o1 + 4];
#pragma unroll
        for (int nf = 0; nf < 16; nf++) {
            int n = nf * 8 + g;
            const uint32_t* b1h = s1h + n * 68;
            const uint32_t* b1l = s1l + n * 68;
            const uint32_t* b2h = s2h + n * 68;
            const uint32_t* b2l = s2l + n * 68;
            uint32_t x0h = b1h[kb + t4], x1h = b1h[kb + t4 + 4];
            uint32_t x0l = b1l[kb + t4], x1l = b1l[kb + t4 + 4];
            uint32_t y0h = b2h[kb + t4], y1h = b2h[kb + t4 + 4];
            uint32_t y0l = b2l[kb + t4], y1l = b2l[kb + t4 + 4];
            mma16816(acc[nf], p0h, p1h, p2h, p3h, x0h, x1h);
            mma16816(acc[nf], p0h, p1h, p2h, p3h, x0l, x1l);
            mma16816(acc[nf], p0l, p1l, p2l, p3l, x0h, x1h);
            mma16816(acc[nf], q0h, q1h, q2h, q3h, y0h, y1h);
            mma16816(acc[nf], q0h, q1h, q2h, q3h, y0l, y1l);
            mma16816(acc[nf], q0l, q1l, q2l, q3l, y0h, y1h);
        }
    }

    int r0 = m0 + g, r1 = m0 + g + 8;
#pragma unroll
    for (int nf = 0; nf < 16; nf++) {
        int c = nf * 8 + t4 * 2;
        float bx = 0.f, by = 0.f;
        if (bias1) { float2 b = *reinterpret_cast<const float2*>(&bias1[c]); bx += b.x; by += b.y; }
        if (bias2) { float2 b = *reinterpret_cast<const float2*>(&bias2[c]); bx += b.x; by += b.y; }
#pragma unroll
        for (int hh = 0; hh < 2; hh++) {
            int r = hh ? r1 : r0;
            if (r >= M) continue;
            float2 o = hh ? make_float2(acc[nf][2] + bx, acc[nf][3] + by)
                          : make_float2(acc[nf][0] + bx, acc[nf][1] + by);
            if (ACCsrc) { float2 d = *reinterpret_cast<const float2*>(&ACCsrc[(size_t)r * 128 + c]); o.x += d.x; o.y += d.y; }
            if (relu) { o.x = fmaxf(o.x, 0.f); o.y = fmaxf(o.y, 0.f); }
            if (Dout) *reinterpret_cast<float2*>(&Dout[(size_t)r * 128 + c]) = o;
            if (Oh) {
                uint32_t h, l;
                split2(o.x, o.y, h, l);
                *reinterpret_cast<uint32_t*>(&Oh[(size_t)r * 128 + c]) = h;
                *reinterpret_cast<uint32_t*>(&Ol[(size_t)r * 128 + c]) = l;
            }
        }
    }
}

// ---------------- gathers (warp per dst row, 2-way unroll — proven) ----------------
__global__ void __launch_bounds__(256) gather_mean_split_kernel(
    const int* __restrict__ off, const int* __restrict__ lst,
    const float* __restrict__ X,
    __nv_bfloat16* __restrict__ Oh, __nv_bfloat16* __restrict__ Ol, int n)
{
    int w = (blockIdx.x * blockDim.x + threadIdx.x) >> 5;
    if (w >= n) return;
    int lane = threadIdx.x & 31;
    int s = off[w], e = off[w + 1];
    float4 a0 = make_float4(0.f, 0.f, 0.f, 0.f);
    float4 a1 = make_float4(0.f, 0.f, 0.f, 0.f);
    int i = s;
    for (; i + 1 < e; i += 2) {
        int p0 = lst[i], p1 = lst[i + 1];
        float4 v0 = *reinterpret_cast<const float4*>(&X[(size_t)p0 * HID + lane * 4]);
        float4 v1 = *reinterpret_cast<const float4*>(&X[(size_t)p1 * HID + lane * 4]);
        a0.x += v0.x; a0.y += v0.y; a0.z += v0.z; a0.w += v0.w;
        a1.x += v1.x; a1.y += v1.y; a1.z += v1.z; a1.w += v1.w;
    }
    if (i < e) {
        int p0 = lst[i];
        float4 v0 = *reinterpret_cast<const float4*>(&X[(size_t)p0 * HID + lane * 4]);
        a0.x += v0.x; a0.y += v0.y; a0.z += v0.z; a0.w += v0.w;
    }
    float inv = 1.0f / fmaxf((float)(e - s), 1.0f);
    float ox = (a0.x + a1.x) * inv, oy = (a0.y + a1.y) * inv;
    float oz = (a0.z + a1.z) * inv, ow = (a0.w + a1.w) * inv;
    uint2 uh, ul;
    split2(ox, oy, uh.x, ul.x);
    split2(oz, ow, uh.y, ul.y);
    reinterpret_cast<uint2*>(&Oh[(size_t)w * HID])[lane] = uh;
    reinterpret_cast<uint2*>(&Ol[(size_t)w * HID])[lane] = ul;
}

// GCN pre-aggregation over x_m (both directions), outputs split GF/GR
__global__ void __launch_bounds__(256) gcn_pre_kernel(const float* __restrict__ X)
{
    int w = (blockIdx.x * blockDim.x + threadIdx.x) >> 5;
    if (w >= NM) return;
    int lane = threadIdx.x & 31;
    size_t ro = (size_t)w * HID + lane * 4;

    float4 aF = make_float4(0.f, 0.f, 0.f, 0.f);
    {
        int s = g_offF[w], e = g_offF[w + 1];
        float4 t1 = make_float4(0.f, 0.f, 0.f, 0.f);
        int i = s;
        for (; i + 1 < e; i += 2) {
            int p0 = g_lstF[i], p1 = g_lstF[i + 1];
            float w0 = g_dF[p0], w1 = g_dF[p1];
            float4 v0 = *reinterpret_cast<const float4*>(&X[(size_t)p0 * HID + lane * 4]);
            float4 v1 = *reinterpret_cast<const float4*>(&X[(size_t)p1 * HID + lane * 4]);
            aF.x += w0 * v0.x; aF.y += w0 * v0.y; aF.z += w0 * v0.z; aF.w += w0 * v0.w;
            t1.x += w1 * v1.x; t1.y += w1 * v1.y; t1.z += w1 * v1.z; t1.w += w1 * v1.w;
        }
        if (i < e) {
            int p0 = g_lstF[i];
            float w0 = g_dF[p0];
            float4 v0 = *reinterpret_cast<const float4*>(&X[(size_t)p0 * HID + lane * 4]);
            aF.x += w0 * v0.x; aF.y += w0 * v0.y; aF.z += w0 * v0.z; aF.w += w0 * v0.w;
        }
        aF.x += t1.x; aF.y += t1.y; aF.z += t1.z; aF.w += t1.w;
    }
    float4 aR = make_float4(0.f, 0.f, 0.f, 0.f);
    {
        int s = g_offR[w], e = g_offR[w + 1];
        float4 t1 = make_float4(0.f, 0.f, 0.f, 0.f);
        int i = s;
        for (; i + 1 < e; i += 2) {
            int p0 = g_lstR[i], p1 = g_lstR[i + 1];
            float w0 = g_dR[p0], w1 = g_dR[p1];
            float4 v0 = *reinterpret_cast<const float4*>(&X[(size_t)p0 * HID + lane * 4]);
            float4 v1 = *reinterpret_cast<const float4*>(&X[(size_t)p1 * HID + lane * 4]);
            aR.x += w0 * v0.x; aR.y += w0 * v0.y; aR.z += w0 * v0.z; aR.w += w0 * v0.w;
            t1.x += w1 * v1.x; t1.y += w1 * v1.y; t1.z += w1 * v1.z; t1.w += w1 * v1.w;
        }
        if (i < e) {
            int p0 = g_lstR[i];
            float w0 = g_dR[p0];
            float4 v0 = *reinterpret_cast<const float4*>(&X[(size_t)p0 * HID + lane * 4]);
            aR.x += w0 * v0.x; aR.y += w0 * v0.y; aR.z += w0 * v0.z; aR.w += w0 * v0.w;
        }
        aR.x += t1.x; aR.y += t1.y; aR.z += t1.z; aR.w += t1.w;
    }

    float f = g_dF[w], r = g_dR[w];
    float f2 = f * f, r2 = r * r;
    float4 xv = *reinterpret_cast<const float4*>(&X[ro]);
    float fx = f * aF.x + f2 * xv.x, fy = f * aF.y + f2 * xv.y;
    float fz = f * aF.z + f2 * xv.z, fw = f * aF.w + f2 * xv.w;
    float rx = r * aR.x + r2 * xv.x, ry = r * aR.y + r2 * xv.y;
    float rz = r * aR.z + r2 * xv.z, rw = r * aR.w + r2 * xv.w;
    uint2 uh, ul;
    split2(fx, fy, uh.x, ul.x);
    split2(fz, fw, uh.y, ul.y);
    reinterpret_cast<uint2*>(&g_GFh[(size_t)w * HID])[lane] = uh;
    reinterpret_cast<uint2*>(&g_GFl[(size_t)w * HID])[lane] = ul;
    split2(rx, ry, uh.x, ul.x);
    split2(rz, rw, uh.y, ul.y);
    reinterpret_cast<uint2*>(&g_GRh[(size_t)w * HID])[lane] = uh;
    reinterpret_cast<uint2*>(&g_GRl[(size_t)w * HID])[lane] = ul;
}

// ---------------- classifier ----------------
__global__ void __launch_bounds__(256) classify_kernel(
    const int* __restrict__ ls, const int* __restrict__ ld,
    const float* __restrict__ XS, const float* __restrict__ XM,
    float* __restrict__ out, int E)
{
    long long t = (long long)blockIdx.x * blockDim.x + threadIdx.x;
    int e = (int)(t >> 5);
    if (e >= E) return;
    int lane = (int)(t & 31);
    int s = ls[e], d = ld[e];
    float4 a = *reinterpret_cast<const float4*>(&XS[(size_t)s * HID + lane * 4]);
    float4 b = *reinterpret_cast<const float4*>(&XM[(size_t)d * HID + lane * 4]);
    float p = a.x * b.x + a.y * b.y + a.z * b.z + a.w * b.w;
#pragma unroll
    for (int o = 16; o > 0; o >>= 1) p += __shfl_xor_sync(0xffffffffu, p, o);
    if (lane == 0) out[e] = p;
}

// ---------------- host ----------------
extern "C" void kernel_launch(void* const* d_in, const int* in_sizes, int n_in,
                              void* d_out, int out_size)
{
    const int*   s2m_src = (const int*)d_in[0];
    const int*   s2m_dst = (const int*)d_in[1];
    const int*   m2m_src = (const int*)d_in[2];
    const int*   m2m_dst = (const int*)d_in[3];
    const int*   lbl_src = (const int*)d_in[4];
    const int*   lbl_dst = (const int*)d_in[5];
    const float* srna    = (const float*)d_in[6];
    const float* mrna    = (const float*)d_in[7];
    const float* sWl     = (const float*)d_in[8];
    const float* sbl     = (const float*)d_in[9];
    const float* sWr     = (const float*)d_in[10];
    const float* rWl     = (const float*)d_in[11];
    const float* rbl     = (const float*)d_in[12];
    const float* rWr     = (const float*)d_in[13];
    const float* gFW     = (const float*)d_in[14];
    const float* gFb     = (const float*)d_in[15];
    const float* gRW     = (const float*)d_in[16];
    const float* gRb     = (const float*)d_in[17];

    const int Es2m = in_sizes[0];
    const int Em2m = in_sizes[2];
    const int Elbl = in_sizes[4];

    float *xs0, *xs1, *xm0, *xm1, *macc;
    int *offMd, *offSs, *lstMd, *lstSs;
    __nv_bfloat16 *Xmh, *Xml, *Magh, *Magl, *GFh, *GFl, *GRh, *GRl;
    __nv_bfloat16 *Xsh, *Xsl, *Sagh, *Sagl, *Wth, *Wtl;
    cudaGetSymbolAddress((void**)&xs0, g_xs0);
    cudaGetSymbolAddress((void**)&xs1, g_xs1);
    cudaGetSymbolAddress((void**)&xm0, g_xm0);
    cudaGetSymbolAddress((void**)&xm1, g_xm1);
    cudaGetSymbolAddress((void**)&macc, g_macc);
    cudaGetSymbolAddress((void**)&offMd, g_offMd);
    cudaGetSymbolAddress((void**)&offSs, g_offSs);
    cudaGetSymbolAddress((void**)&lstMd, g_lstMd);
    cudaGetSymbolAddress((void**)&lstSs, g_lstSs);
    cudaGetSymbolAddress((void**)&Xmh, g_Xmh);
    cudaGetSymbolAddress((void**)&Xml, g_Xml);
    cudaGetSymbolAddress((void**)&Magh, g_Magh);
    cudaGetSymbolAddress((void**)&Magl, g_Magl);
    cudaGetSymbolAddress((void**)&GFh, g_GFh);
    cudaGetSymbolAddress((void**)&GFl, g_GFl);
    cudaGetSymbolAddress((void**)&GRh, g_GRh);
    cudaGetSymbolAddress((void**)&GRl, g_GRl);
    cudaGetSymbolAddress((void**)&Xsh, g_Xsh);
    cudaGetSymbolAddress((void**)&Xsl, g_Xsl);
    cudaGetSymbolAddress((void**)&Sagh, g_Sagh);
    cudaGetSymbolAddress((void**)&Sagl, g_Sagl);
    cudaGetSymbolAddress((void**)&Wth, g_Wth);
    cudaGetSymbolAddress((void**)&Wtl, g_Wtl);

    cudaFuncSetAttribute(gemm_dual,
                         cudaFuncAttributeMaxDynamicSharedMemorySize, DUAL_SMEM);

    static cudaStream_t s2 = nullptr;
    static cudaEvent_t ev0, evCsr, evS;
    static cudaEvent_t evP1[NLAYERS], evM[NLAYERS];
    if (!s2) {
        cudaStreamCreateWithFlags(&s2, cudaStreamNonBlocking);
        cudaEventCreateWithFlags(&ev0, cudaEventDisableTiming);
        cudaEventCreateWithFlags(&evCsr, cudaEventDisableTiming);
        cudaEventCreateWithFlags(&evS, cudaEventDisableTiming);
        for (int i = 0; i < NLAYERS; i++) {
            cudaEventCreateWithFlags(&evP1[i], cudaEventDisableTiming);
            cudaEventCreateWithFlags(&evM[i], cudaEventDisableTiming);
        }
    }

    const size_t WSZ = (size_t)HID * HID;
    const unsigned gm = NMP / 256;   // 392
    const unsigned gs = NSP / 256;   // 79

    // ---- fork: side does initial feature splits; main: batched weight split + CSR ----
    cudaEventRecord(ev0, 0);
    cudaStreamWaitEvent(s2, ev0, 0);
    split_kernel<<<(NM * 32 + 255) / 256, 256, 0, s2>>>(mrna, Xmh, Xml, NM * 32);
    split_kernel<<<(NS * 32 + 255) / 256, 256, 0, s2>>>(srna, Xsh, Xsl, NS * 32);

    {
        WPtrs wp;
        for (int l = 0; l < NLAYERS; l++) {
            wp.p[l * 6 + 0] = sWl + l * WSZ;
            wp.p[l * 6 + 1] = sWr + l * WSZ;
            wp.p[l * 6 + 2] = rWl + l * WSZ;
            wp.p[l * 6 + 3] = rWr + l * WSZ;
            wp.p[l * 6 + 4] = gFW + l * WSZ;
            wp.p[l * 6 + 5] = gRW + l * WSZ;
        }
        dim3 g(64, 12);
        wsplit_all_kernel<<<g, 256>>>(wp);
    }
    zero_counts_kernel<<<(NM + 255) / 256, 256>>>();
    hist_s2m_kernel<<<(Es2m + 255) / 256, 256>>>(s2m_src, s2m_dst, Es2m);
    hist_m2m_kernel<<<(Em2m + 255) / 256, 256>>>(m2m_src, m2m_dst, Em2m);
    {
        dim3 g((NM + 1023) / 1024, 4);
        scan_partial_kernel<<<g, 1024>>>();
        scan_fix_kernel<<<g, 1024>>>();
    }
    fill_s2m_kernel<<<(Es2m + 255) / 256, 256>>>(s2m_src, s2m_dst, Es2m);
    fill_m2m_kernel<<<(Em2m + 255) / 256, 256>>>(m2m_src, m2m_dst, Em2m);
    deg_kernel<<<(NM + 255) / 256, 256>>>();
    cudaEventRecord(evCsr, 0);
    cudaStreamWaitEvent(s2, evCsr, 0);   // side gathers need CSR

    const float* xsi = srna;
    const float* xmi = mrna;

    for (int l = 0; l < NLAYERS; l++) {
        float* xso = (l == 0) ? xs0 : xs1;
        float* xmo = (l == 0) ? xm0 : xm1;
        int s6 = l * 6;

        if (l > 0) cudaStreamWaitEvent(s2, evM[l - 1], 0);  // xm + Xm split from prev pair2

        // ---- side stream: Md gather -> pair1 -> Ss gather -> s-pair ----
        gather_mean_split_kernel<<<(NM * 32 + 255) / 256, 256, 0, s2>>>(offMd, lstMd, xsi, Magh, Magl, NM);
        gemm_dual<<<gm, 512, DUAL_SMEM, s2>>>(
            Xmh, Xml, Wth + (s6 + 1) * WSZ, Wtl + (s6 + 1) * WSZ,     // x_m @ sWr
            Magh, Magl, Wth + (s6 + 0) * WSZ, Wtl + (s6 + 0) * WSZ,   // mean @ sWl
            nullptr, macc, NM, sbl + l * HID, nullptr, 0, nullptr, nullptr);
        cudaEventRecord(evP1[l], s2);
        gather_mean_split_kernel<<<(NS * 32 + 255) / 256, 256, 0, s2>>>(offSs, lstSs, xmi, Sagh, Sagl, NS);
        gemm_dual<<<gs, 512, DUAL_SMEM, s2>>>(
            Xsh, Xsl, Wth + (s6 + 3) * WSZ, Wtl + (s6 + 3) * WSZ,     // x_s @ rWr
            Sagh, Sagl, Wth + (s6 + 2) * WSZ, Wtl + (s6 + 2) * WSZ,   // mean @ rWl
            nullptr, xso, NS, rbl + l * HID, nullptr, 1, Xsh, Xsl);
        if (l == NLAYERS - 1) cudaEventRecord(evS, s2);

        // ---- main stream: gcn_pre (memory) overlaps pair1 (tensor) ----
        gcn_pre_kernel<<<(NM * 32 + 255) / 256, 256>>>(xmi);
        cudaStreamWaitEvent(0, evP1[l], 0);
        gemm_dual<<<gm, 512, DUAL_SMEM>>>(
            GFh, GFl, Wth + (s6 + 4) * WSZ, Wtl + (s6 + 4) * WSZ,     // gF_in @ gFW
            GRh, GRl, Wth + (s6 + 5) * WSZ, Wtl + (s6 + 5) * WSZ,     // gR_in @ gRW
            macc, xmo, NM, gFb + l * HID, gRb + l * HID, 1, Xmh, Xml);
        cudaEventRecord(evM[l], 0);

        xsi = xso;
        xmi = xmo;
    }

    cudaStreamWaitEvent(0, evS, 0);
    {
        long long th = (long long)Elbl * 32;
        classify_kernel<<<(unsigned)((th + 255) / 256), 256>>>(lbl_src, lbl_dst, xsi, xmi, (float*)d_out, Elbl);
    }
}